// round 3
// baseline (speedup 1.0000x reference)
#include <cuda_runtime.h>
#include <cuda_bf16.h>
#include <math.h>

// Problem constants
#define B_   32
#define N_   325
#define K_   20
#define SIN_ 12
#define SOUT_ 12
#define C_   10
#define H_   48        // 4*S_OUT
#define ROWS_ (B_ * N_)          // 10400
#define OUT_DATA_ELEMS (B_ * N_ * C_ * SOUT_)  // 1,248,000

// Device scratch (allocation-free rule: __device__ globals)
__device__ float g_wh[ROWS_ * SOUT_];
__device__ float g_hx[ROWS_ * H_];   // hx + a1_b folded in
__device__ float g_hy[ROWS_ * H_];
__device__ double g_acc[3];          // [0]=cluster-loss sum, [1]=dist sum, [2]=wh sum

__device__ __forceinline__ float leaky(float x) { return x >= 0.0f ? x : 0.5f * x; }

__global__ void zero_acc_kernel() {
    g_acc[0] = 0.0; g_acc[1] = 0.0; g_acc[2] = 0.0;
}

// One thread per (b,n) row: wh = leaky(x @ wW + wb); hx = wh @ a1W[:12] + a1b; hy = wh @ a1W[12:]
__global__ void precompute_kernel(const float* __restrict__ x,
                                  const float* __restrict__ wW,
                                  const float* __restrict__ wb,
                                  const float* __restrict__ a1W,
                                  const float* __restrict__ a1b) {
    int row = blockIdx.x * blockDim.x + threadIdx.x;
    float whsum = 0.0f;
    if (row < ROWS_) {
        float xi[SIN_];
        #pragma unroll
        for (int i = 0; i < SIN_; i++) xi[i] = x[row * SIN_ + i];
        float wh[SOUT_];
        #pragma unroll
        for (int s = 0; s < SOUT_; s++) {
            float a = __ldg(&wb[s]);
            #pragma unroll
            for (int i = 0; i < SIN_; i++) a += xi[i] * __ldg(&wW[i * SOUT_ + s]);
            a = leaky(a);
            wh[s] = a;
            whsum += a;
            g_wh[row * SOUT_ + s] = a;
        }
        #pragma unroll
        for (int c = 0; c < H_; c++) {
            float hx = __ldg(&a1b[c]);
            float hy = 0.0f;
            #pragma unroll
            for (int s = 0; s < SOUT_; s++) {
                hx += wh[s] * __ldg(&a1W[s * H_ + c]);
                hy += wh[s] * __ldg(&a1W[(SOUT_ + s) * H_ + c]);
            }
            g_hx[row * H_ + c] = hx;
            g_hy[row * H_ + c] = hy;
        }
    }
    // block reduce whsum -> one double atomic per block
    #pragma unroll
    for (int o = 16; o > 0; o >>= 1) whsum += __shfl_down_sync(0xffffffffu, whsum, o);
    __shared__ float red[8];
    int lane = threadIdx.x & 31, warp = threadIdx.x >> 5;
    if (lane == 0) red[warp] = whsum;
    __syncthreads();
    if (threadIdx.x == 0) {
        float t = 0.0f;
        int nw = (blockDim.x + 31) >> 5;
        for (int w = 0; w < nw; w++) t += red[w];
        atomicAdd(&g_acc[2], (double)t);
    }
}

// One block (256 threads) per (b,n). Computes gathered attention, softmax,
// output einsum, dist/prob pair losses.
__global__ __launch_bounds__(256) void main_kernel(const int* __restrict__ idx,
                                                   const float* __restrict__ a2W,
                                                   const float* __restrict__ a2b,
                                                   float* __restrict__ out) {
    const int row = blockIdx.x;          // b*N + n
    const int b = row / N_;
    const int tid = threadIdx.x;

    __shared__ float hx_s[H_];
    __shared__ int   m_s[K_];
    __shared__ float h_s[K_][H_];
    __shared__ float am_s[K_][C_];       // logits -> softmax in place
    __shared__ float wt_s[K_][SOUT_];
    __shared__ float wtn_s[K_][SOUT_];
    __shared__ float red_cl[8], red_ds[8];

    if (tid < H_) hx_s[tid] = g_hx[row * H_ + tid];
    if (tid < K_) {
        int m = idx[row * K_ + tid];
        m_s[tid] = m;
        float nrm = 0.0f;
        const float* whrow = &g_wh[(b * N_ + m) * SOUT_];
        #pragma unroll
        for (int s = 0; s < SOUT_; s++) {
            float w = whrow[s];
            wt_s[tid][s] = w;
            nrm += w * w;
        }
        float inv = 1.0f / (sqrtf(nrm) + 1e-8f);
        #pragma unroll
        for (int s = 0; s < SOUT_; s++) wtn_s[tid][s] = wt_s[tid][s] * inv;
    }
    __syncthreads();

    // hidden rows for the K gathered neighbors: h[k][j] = leaky(hx[j] + hy[m_k][j])
    for (int e = tid; e < K_ * H_; e += 256) {
        int k = e / H_, j = e % H_;
        h_s[k][j] = leaky(hx_s[j] + g_hy[(b * N_ + m_s[k]) * H_ + j]);
    }
    __syncthreads();

    // attention logits: 200 threads, one (k,c) each
    if (tid < K_ * C_) {
        int k = tid / C_, c = tid % C_;
        float a = __ldg(&a2b[c]);
        #pragma unroll
        for (int j = 0; j < H_; j++) a += h_s[k][j] * __ldg(&a2W[j * C_ + c]);
        am_s[k][c] = leaky(a);
    }
    __syncthreads();

    // per-k softmax over C
    if (tid < K_) {
        float mx = -1e30f;
        #pragma unroll
        for (int c = 0; c < C_; c++) mx = fmaxf(mx, am_s[tid][c]);
        float e[C_], s = 0.0f;
        #pragma unroll
        for (int c = 0; c < C_; c++) { e[c] = expf(am_s[tid][c] - mx); s += e[c]; }
        float inv = 1.0f / s;
        #pragma unroll
        for (int c = 0; c < C_; c++) am_s[tid][c] = e[c] * inv;
    }
    __syncthreads();

    // output_data[b,n,c,s] = sum_k am[k][c] * wt[k][s]
    if (tid < C_ * SOUT_) {
        int c = tid / SOUT_, s = tid % SOUT_;
        float acc = 0.0f;
        #pragma unroll
        for (int k = 0; k < K_; k++) acc += am_s[k][c] * wt_s[k][s];
        out[(row * C_ + c) * SOUT_ + s] = acc;
    }

    // pair losses: 400 (k,l) pairs
    float cl = 0.0f, ds = 0.0f;
    for (int p = tid; p < K_ * K_; p += 256) {
        int k = p / K_, l = p % K_;
        float d = 0.0f;
        #pragma unroll
        for (int s = 0; s < SOUT_; s++) d += wtn_s[k][s] * wtn_s[l][s];
        ds += d;
        if (k != l) {
            float pr = 0.0f;
            #pragma unroll
            for (int c = 0; c < C_; c++) pr += am_s[k][c] * am_s[l][c];
            pr = fminf(fmaxf(pr, 1e-4f), 1.0f - 1e-4f);
            float lp = logf(pr);
            // cl_elem = -(same*lp - diff*lp); same = (d >= 0.5)
            cl += (d >= 0.5f) ? -lp : lp;
        }
    }
    #pragma unroll
    for (int o = 16; o > 0; o >>= 1) {
        cl += __shfl_down_sync(0xffffffffu, cl, o);
        ds += __shfl_down_sync(0xffffffffu, ds, o);
    }
    int lane = tid & 31, warp = tid >> 5;
    if (lane == 0) { red_cl[warp] = cl; red_ds[warp] = ds; }
    __syncthreads();
    if (tid == 0) {
        float c2 = 0.0f, d2 = 0.0f;
        #pragma unroll
        for (int w = 0; w < 8; w++) { c2 += red_cl[w]; d2 += red_ds[w]; }
        atomicAdd(&g_acc[0], (double)c2);
        atomicAdd(&g_acc[1], (double)d2);
    }
}

__global__ void finalize_kernel(float* __restrict__ out) {
    out[OUT_DATA_ELEMS + 0] = (float)(g_acc[0] / (double)ROWS_);
    out[OUT_DATA_ELEMS + 1] = (float)(g_acc[1] / ((double)ROWS_ * K_ * K_));
    out[OUT_DATA_ELEMS + 2] = (float)(g_acc[2] / ((double)ROWS_ * SOUT_));
}

extern "C" void kernel_launch(void* const* d_in, const int* in_sizes, int n_in,
                              void* d_out, int out_size) {
    // inputs (metadata order):
    // 0: fushed_features (unused by reference)
    // 1: input_data (B,N,S_IN) f32
    // 2: w_W (12,12) f32    3: w_b (12,) f32
    // 4: a1_W (24,48) f32   5: a1_b (48,) f32
    // 6: a2_W (48,10) f32   7: a2_b (10,) f32
    // 8: adj_mx_topk_index (B,N,K) int32
    const float* input_data = (const float*)d_in[1];
    const float* wW  = (const float*)d_in[2];
    const float* wb  = (const float*)d_in[3];
    const float* a1W = (const float*)d_in[4];
    const float* a1b = (const float*)d_in[5];
    const float* a2W = (const float*)d_in[6];
    const float* a2b = (const float*)d_in[7];
    const int*   idx = (const int*)d_in[8];
    float* out = (float*)d_out;

    zero_acc_kernel<<<1, 1>>>();
    precompute_kernel<<<(ROWS_ + 255) / 256, 256>>>(input_data, wW, wb, a1W, a1b);
    main_kernel<<<ROWS_, 256>>>(idx, a2W, a2b, out);
    finalize_kernel<<<1, 1>>>(out);
}

// round 4
// speedup vs baseline: 1.3465x; 1.3465x over previous
#include <cuda_runtime.h>
#include <math.h>

// Problem constants
#define B_    32
#define N_    325
#define K_    20
#define SIN_  12
#define SOUT_ 12
#define C_    10
#define H_    48                    // 4*S_OUT
#define ROWS_ (B_ * N_)             // 10400
#define WPB   4                     // warps (rows) per block
#define GRID_ (ROWS_ / WPB)         // 2600
#define OUT_DATA_ELEMS (ROWS_ * C_ * SOUT_)  // 1,248,000

// padded smem strides (bank-conflict-free)
#define HS_   49   // h row stride
#define AMS_  11   // attention row stride
#define WTS_  13   // wt/wtn row stride

// Device scratch (allocation-free rule: __device__ globals). 16B-aligned for float4.
__device__ __align__(16) float g_wh[ROWS_ * SOUT_];
__device__ __align__(16) float g_hx[ROWS_ * H_];   // hx + a1_b folded in
__device__ __align__(16) float g_hy[ROWS_ * H_];
__device__ double   g_acc[3];      // [0]=cluster-loss, [1]=dist sum, [2]=wh sum (zero-init)
__device__ unsigned g_done;        // completion counter (zero-init)

__device__ __forceinline__ float leaky(float x) { return x >= 0.0f ? x : 0.5f * x; }

// ---------------------------------------------------------------------------
// Warp-per-row precompute: wh = leaky(x@wW+wb); hx = wh@a1W[:12]+a1b; hy = wh@a1W[12:]
// 2600 blocks x 128 threads (4 rows/block). Coalesced 128B output writes.
// ---------------------------------------------------------------------------
__global__ __launch_bounds__(128) void precompute_kernel(
    const float* __restrict__ x,
    const float* __restrict__ wW,  const float* __restrict__ wb,
    const float* __restrict__ a1W, const float* __restrict__ a1b)
{
    __shared__ float wW_s[SIN_ * SOUT_];       // 144
    __shared__ float wb_s[SOUT_];
    __shared__ float a1W_s[2 * SOUT_ * H_];    // 1152
    __shared__ float a1b_s[H_];
    __shared__ float xs[WPB][SIN_];
    __shared__ float whs[WPB][SOUT_];
    __shared__ float red[WPB];

    const int tid = threadIdx.x;
    for (int i = tid; i < SIN_ * SOUT_; i += 128) wW_s[i] = wW[i];
    if (tid < SOUT_) wb_s[tid] = wb[tid];
    for (int i = tid; i < 2 * SOUT_ * H_; i += 128) a1W_s[i] = a1W[i];
    if (tid < H_) a1b_s[tid] = a1b[tid];
    __syncthreads();

    const int warp = tid >> 5, lane = tid & 31;
    const int row = blockIdx.x * WPB + warp;

    if (lane < SIN_) xs[warp][lane] = x[row * SIN_ + lane];
    __syncwarp();

    float whsum = 0.0f;
    if (lane < SOUT_) {
        float a = wb_s[lane];
        #pragma unroll
        for (int i = 0; i < SIN_; i++) a += xs[warp][i] * wW_s[i * SOUT_ + lane];
        a = leaky(a);
        whs[warp][lane] = a;
        g_wh[row * SOUT_ + lane] = a;
        whsum = a;
    }
    __syncwarp();

    // 96 outputs (48 hx + 48 hy) over 32 lanes, 3 iterations, coalesced writes
    #pragma unroll
    for (int it = 0; it < 3; it++) {
        int o = it * 32 + lane;
        bool isx = (o < H_);
        int j = isx ? o : o - H_;
        float a = isx ? a1b_s[j] : 0.0f;
        const float* col = isx ? &a1W_s[j] : &a1W_s[SOUT_ * H_ + j];
        #pragma unroll
        for (int s = 0; s < SOUT_; s++) a += whs[warp][s] * col[s * H_];
        if (isx) g_hx[row * H_ + j] = a;
        else     g_hy[row * H_ + j] = a;
    }

    // reduce whsum (lanes >= 12 contribute 0)
    #pragma unroll
    for (int o = 16; o > 0; o >>= 1) whsum += __shfl_down_sync(0xffffffffu, whsum, o);
    if (lane == 0) red[warp] = whsum;
    __syncthreads();
    if (tid == 0) atomicAdd(&g_acc[2], (double)(red[0] + red[1] + red[2] + red[3]));
}

// ---------------------------------------------------------------------------
// Warp-per-row main: gather neighbors, attention logits, softmax, output einsum,
// pair losses. Last block finalizes scalars and resets accumulators (for graph
// replay determinism).
// ---------------------------------------------------------------------------
__global__ __launch_bounds__(128) void main_kernel(
    const int* __restrict__ idx,
    const float* __restrict__ a2W, const float* __restrict__ a2b,
    float* __restrict__ out)
{
    __shared__ float a2W_s[H_ * C_];   // 480
    __shared__ float a2b_s[C_];
    __shared__ __align__(16) float hx_s[WPB][H_];
    __shared__ float h_s[WPB][K_ * HS_];     // 4 x 980
    __shared__ float am_s[WPB][K_ * AMS_];   // 4 x 220
    __shared__ float wt_s[WPB][K_ * WTS_];   // 4 x 260
    __shared__ float wtn_s[WPB][K_ * WTS_];
    __shared__ int   m_s[WPB][K_];
    __shared__ float red_cl[WPB], red_ds[WPB];
    __shared__ bool  is_last;

    const int tid = threadIdx.x;
    for (int i = tid; i < H_ * C_; i += 128) a2W_s[i] = a2W[i];
    if (tid < C_) a2b_s[tid] = a2b[tid];
    __syncthreads();

    const int warp = tid >> 5, lane = tid & 31;
    const int row = blockIdx.x * WPB + warp;
    const int base_b = (row / N_) * N_;

    // hx row (48 floats = 12 float4)
    if (lane < 12)
        ((float4*)&hx_s[warp][0])[lane] = ((const float4*)&g_hx[row * H_])[lane];

    // neighbor indices, wt (gathered wh rows), wtn (normalized)
    if (lane < K_) {
        int m = idx[row * K_ + lane];
        m_s[warp][lane] = m;
        const float4* wr = (const float4*)&g_wh[(base_b + m) * SOUT_];
        float4 w0 = wr[0], w1 = wr[1], w2 = wr[2];
        float w[SOUT_] = {w0.x, w0.y, w0.z, w0.w, w1.x, w1.y, w1.z, w1.w,
                          w2.x, w2.y, w2.z, w2.w};
        float nrm = 0.0f;
        #pragma unroll
        for (int s = 0; s < SOUT_; s++) nrm += w[s] * w[s];
        float inv = 1.0f / (sqrtf(nrm) + 1e-8f);
        #pragma unroll
        for (int s = 0; s < SOUT_; s++) {
            wt_s[warp][lane * WTS_ + s]  = w[s];
            wtn_s[warp][lane * WTS_ + s] = w[s] * inv;
        }
    }
    __syncwarp();

    // hidden rows: h[k][j] = leaky(hx[j] + hy[m_k][j]); 240 float4 items
    for (int e = lane; e < K_ * 12; e += 32) {
        int k = e / 12, q = e % 12;
        float4 v   = *(const float4*)&g_hy[(base_b + m_s[warp][k]) * H_ + q * 4];
        float4 hx4 = *(const float4*)&hx_s[warp][q * 4];
        float* hp = &h_s[warp][k * HS_ + q * 4];
        hp[0] = leaky(hx4.x + v.x);
        hp[1] = leaky(hx4.y + v.y);
        hp[2] = leaky(hx4.z + v.z);
        hp[3] = leaky(hx4.w + v.w);
    }
    __syncwarp();

    // attention logits: 200 (k,c) items
    #pragma unroll
    for (int it = 0; it < 7; it++) {
        int item = it * 32 + lane;
        if (item < K_ * C_) {
            int k = item / C_, c = item % C_;
            float a = a2b_s[c];
            const float* hr = &h_s[warp][k * HS_];
            #pragma unroll
            for (int j = 0; j < H_; j++) a += hr[j] * a2W_s[j * C_ + c];
            am_s[warp][k * AMS_ + c] = leaky(a);
        }
    }
    __syncwarp();

    // per-k softmax over C
    if (lane < K_) {
        float* ar = &am_s[warp][lane * AMS_];
        float mx = ar[0];
        #pragma unroll
        for (int c = 1; c < C_; c++) mx = fmaxf(mx, ar[c]);
        float e[C_], s = 0.0f;
        #pragma unroll
        for (int c = 0; c < C_; c++) { e[c] = expf(ar[c] - mx); s += e[c]; }
        float inv = 1.0f / s;
        #pragma unroll
        for (int c = 0; c < C_; c++) ar[c] = e[c] * inv;
    }
    __syncwarp();

    // output_data[b,n,c,s] = sum_k am[k][c] * wt[k][s]; coalesced writes
    #pragma unroll
    for (int it = 0; it < 4; it++) {
        int item = it * 32 + lane;
        if (item < C_ * SOUT_) {
            int c = item / SOUT_, s = item % SOUT_;
            float acc = 0.0f;
            #pragma unroll
            for (int k = 0; k < K_; k++)
                acc += am_s[warp][k * AMS_ + c] * wt_s[warp][k * WTS_ + s];
            out[row * (C_ * SOUT_) + item] = acc;
        }
    }

    // pair losses: 400 (k,l) pairs
    float cl = 0.0f, ds = 0.0f;
    #pragma unroll 1
    for (int it = 0; it < 13; it++) {
        int p = it * 32 + lane;
        if (p < K_ * K_) {
            int k = p / K_, l = p % K_;
            float d = 0.0f;
            #pragma unroll
            for (int s = 0; s < SOUT_; s++)
                d += wtn_s[warp][k * WTS_ + s] * wtn_s[warp][l * WTS_ + s];
            ds += d;
            if (k != l) {
                float pr = 0.0f;
                #pragma unroll
                for (int c = 0; c < C_; c++)
                    pr += am_s[warp][k * AMS_ + c] * am_s[warp][l * AMS_ + c];
                pr = fminf(fmaxf(pr, 1e-4f), 1.0f - 1e-4f);
                float lp = logf(pr);
                cl += (d >= 0.5f) ? -lp : lp;   // -(same - diff)*log(p)
            }
        }
    }
    #pragma unroll
    for (int o = 16; o > 0; o >>= 1) {
        cl += __shfl_down_sync(0xffffffffu, cl, o);
        ds += __shfl_down_sync(0xffffffffu, ds, o);
    }
    if (lane == 0) { red_cl[warp] = cl; red_ds[warp] = ds; }
    __syncthreads();
    if (tid == 0) {
        atomicAdd(&g_acc[0], (double)(red_cl[0] + red_cl[1] + red_cl[2] + red_cl[3]));
        atomicAdd(&g_acc[1], (double)(red_ds[0] + red_ds[1] + red_ds[2] + red_ds[3]));
        __threadfence();
        unsigned v = atomicAdd(&g_done, 1u);
        is_last = (v == gridDim.x - 1);
    }
    __syncthreads();

    // last block finalizes the three scalar means and resets state for replay
    if (is_last && tid == 0) {
        double c0 = atomicAdd(&g_acc[0], 0.0);
        double c1 = atomicAdd(&g_acc[1], 0.0);
        double c2 = atomicAdd(&g_acc[2], 0.0);
        out[OUT_DATA_ELEMS + 0] = (float)(c0 / (double)ROWS_);
        out[OUT_DATA_ELEMS + 1] = (float)(c1 / ((double)ROWS_ * K_ * K_));
        out[OUT_DATA_ELEMS + 2] = (float)(c2 / ((double)ROWS_ * SOUT_));
        g_acc[0] = 0.0; g_acc[1] = 0.0; g_acc[2] = 0.0;
        __threadfence();
        g_done = 0;
    }
}

extern "C" void kernel_launch(void* const* d_in, const int* in_sizes, int n_in,
                              void* d_out, int out_size) {
    // inputs (metadata order):
    // 0: fushed_features (unused)   1: input_data (B,N,12) f32
    // 2: w_W (12,12)  3: w_b (12,)  4: a1_W (24,48)  5: a1_b (48,)
    // 6: a2_W (48,10) 7: a2_b (10,) 8: adj_mx_topk_index (B,N,20) i32
    const float* input_data = (const float*)d_in[1];
    const float* wW  = (const float*)d_in[2];
    const float* wb  = (const float*)d_in[3];
    const float* a1W = (const float*)d_in[4];
    const float* a1b = (const float*)d_in[5];
    const float* a2W = (const float*)d_in[6];
    const float* a2b = (const float*)d_in[7];
    const int*   idx = (const int*)d_in[8];
    float* out = (float*)d_out;

    precompute_kernel<<<GRID_, 128>>>(input_data, wW, wb, a1W, a1b);
    main_kernel<<<GRID_, 128>>>(idx, a2W, a2b, out);
}

// round 7
// speedup vs baseline: 2.0823x; 1.5464x over previous
#include <cuda_runtime.h>
#include <math.h>

// Problem constants
#define B_    32
#define N_    325
#define K_    20
#define SIN_  12
#define SOUT_ 12
#define C_    10
#define H_    48                    // 4*S_OUT
#define ROWS_ (B_ * N_)             // 10400
#define WPB   4                     // warps (rows) per block
#define GRID_ (ROWS_ / WPB)         // 2600
#define OUT_DATA_ELEMS (ROWS_ * C_ * SOUT_)  // 1,248,000

// padded smem strides (bank-conflict-free)
#define AMS_  11   // attention row stride
#define WTS_  13   // wt row stride

// Device scratch (allocation-free rule: __device__ globals). 16B-aligned for float4.
__device__ __align__(16) float g_wh[ROWS_ * SOUT_];
__device__ __align__(16) float g_hx[ROWS_ * H_];   // hx + a1_b folded in
__device__ __align__(16) float g_hy[ROWS_ * H_];
__device__ double   g_acc[3];      // [0]=cluster-loss, [1]=dist sum, [2]=wh sum (zero-init)
__device__ unsigned g_done;        // completion counter (zero-init)

__device__ __forceinline__ float leaky(float x) { return x >= 0.0f ? x : 0.5f * x; }

// ---------------------------------------------------------------------------
// Warp-per-row precompute: wh = leaky(x@wW+wb); hx = wh@a1W[:12]+a1b; hy = wh@a1W[12:]
// ---------------------------------------------------------------------------
__global__ __launch_bounds__(128) void precompute_kernel(
    const float* __restrict__ x,
    const float* __restrict__ wW,  const float* __restrict__ wb,
    const float* __restrict__ a1W, const float* __restrict__ a1b)
{
    __shared__ float wW_s[SIN_ * SOUT_];       // 144
    __shared__ float wb_s[SOUT_];
    __shared__ float a1W_s[2 * SOUT_ * H_];    // 1152
    __shared__ float a1b_s[H_];
    __shared__ float xs[WPB][SIN_];
    __shared__ float whs[WPB][SOUT_];
    __shared__ float red[WPB];

    const int tid = threadIdx.x;
    for (int i = tid; i < SIN_ * SOUT_; i += 128) wW_s[i] = wW[i];
    if (tid < SOUT_) wb_s[tid] = wb[tid];
    for (int i = tid; i < 2 * SOUT_ * H_; i += 128) a1W_s[i] = a1W[i];
    if (tid < H_) a1b_s[tid] = a1b[tid];
    __syncthreads();

    const int warp = tid >> 5, lane = tid & 31;
    const int row = blockIdx.x * WPB + warp;

    if (lane < SIN_) xs[warp][lane] = x[row * SIN_ + lane];
    __syncwarp();

    float whsum = 0.0f;
    if (lane < SOUT_) {
        float a = wb_s[lane];
        #pragma unroll
        for (int i = 0; i < SIN_; i++) a += xs[warp][i] * wW_s[i * SOUT_ + lane];
        a = leaky(a);
        whs[warp][lane] = a;
        g_wh[row * SOUT_ + lane] = a;
        whsum = a;
    }
    __syncwarp();

    // 96 outputs (48 hx + 48 hy) over 32 lanes, coalesced writes
    #pragma unroll
    for (int it = 0; it < 3; it++) {
        int o = it * 32 + lane;
        bool isx = (o < H_);
        int j = isx ? o : o - H_;
        float a = isx ? a1b_s[j] : 0.0f;
        const float* col = isx ? &a1W_s[j] : &a1W_s[SOUT_ * H_ + j];
        #pragma unroll
        for (int s = 0; s < SOUT_; s++) a += whs[warp][s] * col[s * H_];
        if (isx) g_hx[row * H_ + j] = a;
        else     g_hy[row * H_ + j] = a;
    }

    #pragma unroll
    for (int o = 16; o > 0; o >>= 1) whsum += __shfl_down_sync(0xffffffffu, whsum, o);
    if (lane == 0) red[warp] = whsum;
    __syncthreads();
    if (tid == 0) atomicAdd(&g_acc[2], (double)(red[0] + red[1] + red[2] + red[3]));
}

// ---------------------------------------------------------------------------
// Warp-per-row main, lane-owns-k dataflow: lanes 0..19 each own one neighbor.
// wt/wtn/am in registers; h transient; pair losses via shuffles w/ symmetry.
// ---------------------------------------------------------------------------
__global__ __launch_bounds__(128) void main_kernel(
    const int* __restrict__ idx,
    const float* __restrict__ a2W, const float* __restrict__ a2b,
    float* __restrict__ out)
{
    __shared__ __align__(16) float a2W_s[H_ * 12];    // [48][12] padded rows
    __shared__ float a2b_s[16];
    __shared__ __align__(16) float hx_s[WPB][H_];
    __shared__ float am_s[WPB][K_ * AMS_];
    __shared__ float wt_s[WPB][K_ * WTS_];
    __shared__ float red_cl[WPB], red_ds[WPB];
    __shared__ bool  is_last;

    const int tid = threadIdx.x;
    // repack a2W (48x10) into padded 48x12 rows (float4-aligned)
    for (int i = tid; i < H_ * 12; i += 128) {
        int j = i / 12, c = i % 12;
        a2W_s[i] = (c < C_) ? a2W[j * C_ + c] : 0.0f;
    }
    if (tid < C_) a2b_s[tid] = a2b[tid];
    __syncthreads();

    const int warp = tid >> 5, lane = tid & 31;
    const int row = blockIdx.x * WPB + warp;
    const int base_b = (row / N_) * N_;

    if (lane < 12)
        ((float4*)hx_s[warp])[lane] = ((const float4*)&g_hx[row * H_])[lane];

    // gather wh[m] -> wt, wtn (registers)
    int m = 0;
    float wt[SOUT_], wtn[SOUT_];
    if (lane < K_) {
        m = idx[row * K_ + lane];
        const float4* wr = (const float4*)&g_wh[(base_b + m) * SOUT_];
        float4 w0 = wr[0], w1 = wr[1], w2 = wr[2];
        wt[0]=w0.x; wt[1]=w0.y; wt[2]=w0.z; wt[3]=w0.w;
        wt[4]=w1.x; wt[5]=w1.y; wt[6]=w1.z; wt[7]=w1.w;
        wt[8]=w2.x; wt[9]=w2.y; wt[10]=w2.z; wt[11]=w2.w;
        float nrm = 0.0f;
        #pragma unroll
        for (int s = 0; s < SOUT_; s++) nrm += wt[s] * wt[s];
        float inv = 1.0f / (sqrtf(nrm) + 1e-8f);
        #pragma unroll
        for (int s = 0; s < SOUT_; s++) wtn[s] = wt[s] * inv;
    } else {
        #pragma unroll
        for (int s = 0; s < SOUT_; s++) { wt[s] = 0.0f; wtn[s] = 0.0f; }
    }
    __syncwarp();   // hx_s ready

    // attention logits: am[c] = a2b[c] + sum_j leaky(hx[j]+hy[m][j]) * a2W[j][c]
    float am[C_];
    #pragma unroll
    for (int c = 0; c < C_; c++) am[c] = a2b_s[c];

    const float4* hyrow = (const float4*)&g_hy[(base_b + m) * H_];
    #pragma unroll
    for (int q = 0; q < 12; q++) {
        float4 hy4 = hyrow[q];
        float4 hx4 = ((const float4*)hx_s[warp])[q];
        float hh[4];
        hh[0] = leaky(hx4.x + hy4.x);
        hh[1] = leaky(hx4.y + hy4.y);
        hh[2] = leaky(hx4.z + hy4.z);
        hh[3] = leaky(hx4.w + hy4.w);
        #pragma unroll
        for (int jj = 0; jj < 4; jj++) {
            const float4* wrow = (const float4*)&a2W_s[(q * 4 + jj) * 12];
            float4 wa = wrow[0], wb4 = wrow[1], wc4 = wrow[2];
            float h = hh[jj];
            am[0] += h * wa.x;  am[1] += h * wa.y;
            am[2] += h * wa.z;  am[3] += h * wa.w;
            am[4] += h * wb4.x; am[5] += h * wb4.y;
            am[6] += h * wb4.z; am[7] += h * wb4.w;
            am[8] += h * wc4.x; am[9] += h * wc4.y;
        }
    }

    // leaky + softmax over C (all lanes run; only lanes<K matter)
    #pragma unroll
    for (int c = 0; c < C_; c++) am[c] = leaky(am[c]);
    float mx = am[0];
    #pragma unroll
    for (int c = 1; c < C_; c++) mx = fmaxf(mx, am[c]);
    float ssum = 0.0f;
    #pragma unroll
    for (int c = 0; c < C_; c++) { am[c] = __expf(am[c] - mx); ssum += am[c]; }
    float sinv = 1.0f / ssum;
    #pragma unroll
    for (int c = 0; c < C_; c++) am[c] *= sinv;

    // stage am, wt for the output einsum
    if (lane < K_) {
        #pragma unroll
        for (int s = 0; s < SOUT_; s++) wt_s[warp][lane * WTS_ + s] = wt[s];
        #pragma unroll
        for (int c = 0; c < C_; c++)   am_s[warp][lane * AMS_ + c] = am[c];
    }
    __syncwarp();

    // output_data[b,n,c,s] = sum_k am[k][c] * wt[k][s] (coalesced writes)
    #pragma unroll
    for (int it = 0; it < 4; it++) {
        int item = it * 32 + lane;
        if (item < C_ * SOUT_) {
            int c = item / SOUT_, s = item % SOUT_;
            float acc = 0.0f;
            #pragma unroll
            for (int k = 0; k < K_; k++)
                acc += am_s[warp][k * AMS_ + c] * wt_s[warp][k * WTS_ + s];
            out[row * (C_ * SOUT_) + item] = acc;
        }
    }

    // pair losses via register shuffles, exploiting S(o) == S(20-o):
    // total = 2*sum_{o=1..9} S(o) + S(10) + diagonal (dist only)
    float cl2 = 0.0f, ds2 = 0.0f, cl10 = 0.0f, ds10 = 0.0f;
    #pragma unroll
    for (int o = 1; o <= 10; o++) {
        int src = lane + o; if (src >= K_) src -= K_;
        float d = 0.0f, pr = 0.0f;
        #pragma unroll
        for (int s = 0; s < SOUT_; s++)
            d += wtn[s] * __shfl_sync(0xffffffffu, wtn[s], src);
        #pragma unroll
        for (int c = 0; c < C_; c++)
            pr += am[c] * __shfl_sync(0xffffffffu, am[c], src);
        pr = fminf(fmaxf(pr, 1e-4f), 1.0f - 1e-4f);
        float lp = __logf(pr);
        float f = (d >= 0.5f) ? -lp : lp;   // -(same - diff)*log(p)
        if (o < 10) { cl2 += f; ds2 += d; }
        else        { cl10 = f; ds10 = d; }
    }
    float dd = 0.0f;
    #pragma unroll
    for (int s = 0; s < SOUT_; s++) dd += wtn[s] * wtn[s];

    float cl = 0.0f, ds = 0.0f;
    if (lane < K_) {
        cl = 2.0f * cl2 + cl10;
        ds = 2.0f * ds2 + ds10 + dd;
    }
    #pragma unroll
    for (int o = 16; o > 0; o >>= 1) {
        cl += __shfl_down_sync(0xffffffffu, cl, o);
        ds += __shfl_down_sync(0xffffffffu, ds, o);
    }
    if (lane == 0) { red_cl[warp] = cl; red_ds[warp] = ds; }
    __syncthreads();
    if (tid == 0) {
        atomicAdd(&g_acc[0], (double)(red_cl[0] + red_cl[1] + red_cl[2] + red_cl[3]));
        atomicAdd(&g_acc[1], (double)(red_ds[0] + red_ds[1] + red_ds[2] + red_ds[3]));
        __threadfence();
        unsigned v = atomicAdd(&g_done, 1u);
        is_last = (v == gridDim.x - 1);
    }
    __syncthreads();

    // last block finalizes scalar means and resets state for graph replay
    if (is_last && tid == 0) {
        double c0 = atomicAdd(&g_acc[0], 0.0);
        double c1 = atomicAdd(&g_acc[1], 0.0);
        double c2 = atomicAdd(&g_acc[2], 0.0);
        out[OUT_DATA_ELEMS + 0] = (float)(c0 / (double)ROWS_);
        out[OUT_DATA_ELEMS + 1] = (float)(c1 / ((double)ROWS_ * K_ * K_));
        out[OUT_DATA_ELEMS + 2] = (float)(c2 / ((double)ROWS_ * SOUT_));
        g_acc[0] = 0.0; g_acc[1] = 0.0; g_acc[2] = 0.0;
        __threadfence();
        g_done = 0;
    }
}

extern "C" void kernel_launch(void* const* d_in, const int* in_sizes, int n_in,
                              void* d_out, int out_size) {
    // inputs (metadata order):
    // 0: fushed_features (unused)   1: input_data (B,N,12) f32
    // 2: w_W (12,12)  3: w_b (12,)  4: a1_W (24,48)  5: a1_b (48,)
    // 6: a2_W (48,10) 7: a2_b (10,) 8: adj_mx_topk_index (B,N,20) i32
    const float* input_data = (const float*)d_in[1];
    const float* wW  = (const float*)d_in[2];
    const float* wb  = (const float*)d_in[3];
    const float* a1W = (const float*)d_in[4];
    const float* a1b = (const float*)d_in[5];
    const float* a2W = (const float*)d_in[6];
    const float* a2b = (const float*)d_in[7];
    const int*   idx = (const int*)d_in[8];
    float* out = (float*)d_out;

    precompute_kernel<<<GRID_, 128>>>(input_data, wW, wb, a1W, a1b);
    main_kernel<<<GRID_, 128>>>(idx, a2W, a2b, out);
}